// round 3
// baseline (speedup 1.0000x reference)
#include <cuda_runtime.h>
#include <cuda_bf16.h>

#define NQ        12
#define BLK       256
#define OUTDIM    256
#define HID       64

__device__ __forceinline__ float2 cmul(float2 a, float2 b) {
    return make_float2(a.x * b.x - a.y * b.y, a.x * b.y + a.y * b.x);
}

__device__ __forceinline__ float2 cfma2(float2 ca, float2 a, float2 cb, float2 b) {
    float2 n;
    n.x = ca.x * a.x - ca.y * a.y + cb.x * b.x - cb.y * b.y;
    n.y = ca.x * a.y + ca.y * a.x + cb.x * b.y + cb.y * b.x;
    return n;
}

__device__ __forceinline__ float2 shflx(float2 v, int m) {
    float2 r;
    r.x = __shfl_xor_sync(0xFFFFFFFFu, v.x, m);
    r.y = __shfl_xor_sync(0xFFFFFFFFu, v.y, m);
    return r;
}

__global__ __launch_bounds__(BLK) void quantum_reupload_kernel(
    const float* __restrict__ x,    // [B, 48]
    const float* __restrict__ rw,   // [12, 3, 4]
    const float* __restrict__ rb,   // [12, 3]
    const float* __restrict__ w1,   // [64, 12]
    const float* __restrict__ b1,   // [64]
    const float* __restrict__ w2,   // [256, 64]
    const float* __restrict__ b2,   // [256]
    float* __restrict__ out)        // [B, 256]
{
    __shared__ float2 st[4096];          // 32 KB exchange buffer
    __shared__ float2 U[NQ][4];
    __shared__ float  zred[NQ][BLK/32];
    __shared__ float  zfin[NQ];
    __shared__ float  hbuf[HID];

    const int b    = blockIdx.x;
    const int tid  = threadIdx.x;
    const int lane = tid & 31;
    const int warp = tid >> 5;

    // L(b) columns for bits 11..8 (k part in mapping B), precomputed GF(2) table.
    // L = composite of the 12-CNOT ring; index bit p of L(b) = XOR of b bits p..11
    // (p<=10), bit 11 = XOR of b bits 0..10.
    const int LK[16] = {0x000,0x9FF,0xBFF,0x200,0xFFF,0x600,0x400,0xDFF,
                        0x7FF,0xE00,0xC00,0x5FF,0x800,0x1FF,0x3FF,0xA00};

    // ---- per-batch U3 matrices (layer-invariant) ----
    if (tid < NQ) {
        const float* xb  = x  + b * 48 + tid * 4;
        const float* rwi = rw + tid * 12;
        const float* rbi = rb + tid * 3;
        float x0 = xb[0], x1 = xb[1], x2 = xb[2], x3 = xb[3];
        float th = rbi[0] + rwi[0]*x0 + rwi[1]*x1 + rwi[2] *x2 + rwi[3] *x3;
        float ph = rbi[1] + rwi[4]*x0 + rwi[5]*x1 + rwi[6] *x2 + rwi[7] *x3;
        float lm = rbi[2] + rwi[8]*x0 + rwi[9]*x1 + rwi[10]*x2 + rwi[11]*x3;
        float sh, ch, sp, cp, sl, cl;
        sincosf(th * 0.5f, &sh, &ch);
        sincosf(ph,        &sp, &cp);
        sincosf(lm,        &sl, &cl);
        U[tid][0] = make_float2(ch, 0.f);
        U[tid][1] = make_float2(-cl * sh, -sl * sh);
        U[tid][2] = make_float2( cp * sh,  sp * sh);
        U[tid][3] = make_float2((cp*cl - sp*sl) * ch, (cp*sl + sp*cl) * ch);
    }
    __syncthreads();

    // per-thread permutation base: Ltid = L(tid) via suffix-parity scan
    int y = tid; y ^= y >> 1; y ^= y >> 2; y ^= y >> 4;
    const int Ltid = y | ((y & 1) << 11);

    float2 a[16];

    // ===== layer 0: state after 12 U3s on |0..0> is a tensor product =====
    // Build directly in mapping B: idx = (k<<8)|tid; wire w <-> idx bit (11-w).
    {
        float2 base = ((tid >> 7) & 1) ? U[4][2] : U[4][0];
        #pragma unroll
        for (int w = 5; w < 12; w++)
            base = cmul(base, ((tid >> (11 - w)) & 1) ? U[w][2] : U[w][0]);
        float2 phi[4], plo[4];
        #pragma unroll
        for (int i = 0; i < 4; i++) {
            phi[i] = cmul((i & 2) ? U[0][2] : U[0][0], (i & 1) ? U[1][2] : U[1][0]);
            plo[i] = cmul((i & 2) ? U[2][2] : U[2][0], (i & 1) ? U[3][2] : U[3][0]);
        }
        #pragma unroll
        for (int k = 0; k < 16; k++)
            a[k] = cmul(base, cmul(phi[k >> 2], plo[k & 3]));
    }

    // CNOT-ring permutation fused into the smem write: st[L(b)] = amp(b)
    #pragma unroll
    for (int k = 0; k < 16; k++)
        st[Ltid ^ LK[k]] = a[k];
    __syncthreads();
    // read back in mapping A: idx = (tid<<4)|k, vectorized + staggered
    {
        float4* st4 = (float4*)st;
        #pragma unroll
        for (int jj = 0; jj < 8; jj++) {
            int j = (jj + lane) & 7;
            float4 v = st4[(tid << 3) | j];
            a[2*j]   = make_float2(v.x, v.y);
            a[2*j+1] = make_float2(v.z, v.w);
        }
    }

    // ===== layers 1,2: 12 U3s then fused CNOT permutation =====
    #pragma unroll
    for (int layer = 1; layer < 3; layer++) {
        // A-phase: wires 3..7 via shfl on lane bit (7-w)
        #pragma unroll
        for (int w = 3; w < 8; w++) {
            const int lb = 7 - w;
            float2 u00 = U[w][0], u01 = U[w][1], u10 = U[w][2], u11 = U[w][3];
            bool hi = (lane >> lb) & 1;
            float2 ca = hi ? u11 : u00;
            float2 cb = hi ? u10 : u01;
            #pragma unroll
            for (int k = 0; k < 16; k++) {
                float2 p = shflx(a[k], 1 << lb);
                a[k] = cfma2(ca, a[k], cb, p);
            }
        }
        // A-phase: wires 8..11 register-local on k bit (11-w)
        #pragma unroll
        for (int w = 8; w < 12; w++) {
            const int bp = 11 - w;
            float2 u00 = U[w][0], u01 = U[w][1], u10 = U[w][2], u11 = U[w][3];
            #pragma unroll
            for (int k0 = 0; k0 < 16; k0++) {
                if (k0 & (1 << bp)) continue;
                const int k1 = k0 | (1 << bp);
                float2 a0 = a[k0], a1 = a[k1];
                a[k0] = cfma2(u00, a0, u01, a1);
                a[k1] = cfma2(u10, a0, u11, a1);
            }
        }

        // transpose A -> B (vectorized write, staggered; plain float2 read)
        __syncthreads();
        {
            float4* st4 = (float4*)st;
            #pragma unroll
            for (int jj = 0; jj < 8; jj++) {
                int j = (jj + lane) & 7;
                st4[(tid << 3) | j] = make_float4(a[2*j].x, a[2*j].y,
                                                  a[2*j+1].x, a[2*j+1].y);
            }
        }
        __syncthreads();
        #pragma unroll
        for (int k = 0; k < 16; k++)
            a[k] = st[(k << 8) | tid];

        // B-phase: wires 0,1,2 on k bits 3,2,1
        #pragma unroll
        for (int w = 0; w < 3; w++) {
            const int bp = 3 - w;
            float2 u00 = U[w][0], u01 = U[w][1], u10 = U[w][2], u11 = U[w][3];
            #pragma unroll
            for (int k0 = 0; k0 < 16; k0++) {
                if (k0 & (1 << bp)) continue;
                const int k1 = k0 | (1 << bp);
                float2 a0 = a[k0], a1 = a[k1];
                a[k0] = cfma2(u00, a0, u01, a1);
                a[k1] = cfma2(u10, a0, u11, a1);
            }
        }

        // fused CNOT-ring permutation: write st[L(b)], read plain A mapping
        __syncthreads();
        #pragma unroll
        for (int k = 0; k < 16; k++)
            st[Ltid ^ LK[k]] = a[k];
        __syncthreads();
        {
            float4* st4 = (float4*)st;
            #pragma unroll
            for (int jj = 0; jj < 8; jj++) {
                int j = (jj + lane) & 7;
                float4 v = st4[(tid << 3) | j];
                a[2*j]   = make_float2(v.x, v.y);
                a[2*j+1] = make_float2(v.z, v.w);
            }
        }
    }

    // ---- Pauli-Z expectations (mapping A: bits 11..4 = tid, 3..0 = k) ----
    float psum = 0.f, s8 = 0.f, s9 = 0.f, s10 = 0.f, s11 = 0.f;
    #pragma unroll
    for (int k = 0; k < 16; k++) {
        float pr = a[k].x * a[k].x + a[k].y * a[k].y;
        psum += pr;
        s8  += ((k >> 3) & 1) ? -pr : pr;
        s9  += ((k >> 2) & 1) ? -pr : pr;
        s10 += ((k >> 1) & 1) ? -pr : pr;
        s11 += ( k       & 1) ? -pr : pr;
    }
    float zl[NQ];
    #pragma unroll
    for (int w = 0; w < 8; w++)
        zl[w] = ((tid >> (7 - w)) & 1) ? -psum : psum;
    zl[8] = s8; zl[9] = s9; zl[10] = s10; zl[11] = s11;

    #pragma unroll
    for (int w = 0; w < NQ; w++) {
        #pragma unroll
        for (int off = 16; off > 0; off >>= 1)
            zl[w] += __shfl_xor_sync(0xFFFFFFFFu, zl[w], off);
    }
    if (lane == 0) {
        #pragma unroll
        for (int w = 0; w < NQ; w++) zred[w][warp] = zl[w];
    }
    __syncthreads();
    if (tid < NQ) {
        float z = 0.f;
        #pragma unroll
        for (int j = 0; j < BLK / 32; j++) z += zred[tid][j];
        zfin[tid] = z;
    }
    __syncthreads();

    // ---- MLP: relu(z @ w1^T + b1) @ w2^T + b2 ----
    if (tid < HID) {
        float h = b1[tid];
        #pragma unroll
        for (int i = 0; i < NQ; i++) h += zfin[i] * w1[tid * NQ + i];
        hbuf[tid] = fmaxf(h, 0.f);
    }
    __syncthreads();
    float o = b2[tid];
    #pragma unroll
    for (int j = 0; j < HID; j++) o += hbuf[j] * w2[tid * HID + j];
    out[b * OUTDIM + tid] = o;
}

extern "C" void kernel_launch(void* const* d_in, const int* in_sizes, int n_in,
                              void* d_out, int out_size) {
    const float* x  = (const float*)d_in[0];
    const float* rw = (const float*)d_in[1];
    const float* rb = (const float*)d_in[2];
    const float* w1 = (const float*)d_in[3];
    const float* b1 = (const float*)d_in[4];
    const float* w2 = (const float*)d_in[5];
    const float* b2 = (const float*)d_in[6];
    float* out = (float*)d_out;
    int batch = in_sizes[0] / 48;
    quantum_reupload_kernel<<<batch, BLK>>>(x, rw, rb, w1, b1, w2, b2, out);
}

// round 4
// speedup vs baseline: 2.0706x; 2.0706x over previous
#include <cuda_runtime.h>
#include <cuda_bf16.h>

#define NQ        12
#define BLK       256
#define OUTDIM    256
#define HID       64

__device__ __forceinline__ float2 cmul(float2 a, float2 b) {
    return make_float2(a.x * b.x - a.y * b.y, a.x * b.y + a.y * b.x);
}

__device__ __forceinline__ float2 cfma2(float2 ca, float2 a, float2 cb, float2 b) {
    float2 n;
    n.x = ca.x * a.x - ca.y * a.y + cb.x * b.x - cb.y * b.y;
    n.y = ca.x * a.y + ca.y * a.x + cb.x * b.y + cb.y * b.x;
    return n;
}

__device__ __forceinline__ float2 shflx(float2 v, int m) {
    float2 r;
    r.x = __shfl_xor_sync(0xFFFFFFFFu, v.x, m);
    r.y = __shfl_xor_sync(0xFFFFFFFFu, v.y, m);
    return r;
}

// CNOT-ring composite permutation L, restricted to index bits 11..8 (the k part
// of mapping B). Verified in R3 (passed correctness).
__constant__ int c_LK_unused[1];  // (keep constant bank untouched; LK is constexpr below)

__global__ __launch_bounds__(BLK) void quantum_reupload_kernel(
    const float* __restrict__ x,    // [B, 48]
    const float* __restrict__ rw,   // [12, 3, 4]
    const float* __restrict__ rb,   // [12, 3]
    const float* __restrict__ w1,   // [64, 12]
    const float* __restrict__ b1,   // [64]
    const float* __restrict__ w2,   // [256, 64]
    const float* __restrict__ b2,   // [256]
    float* __restrict__ out)        // [B, 256]
{
    __shared__ float2 st[4096];          // 32 KB exchange buffer
    __shared__ float2 U[NQ][4];
    __shared__ float  zred[NQ][BLK/32];
    __shared__ float  zfin[NQ];
    __shared__ float  hbuf[HID];

    const int b    = blockIdx.x;
    const int tid  = threadIdx.x;
    const int lane = tid & 31;
    const int warp = tid >> 5;

    constexpr int LK[16] = {0x000,0x9FF,0xBFF,0x200,0xFFF,0x600,0x400,0xDFF,
                            0x7FF,0xE00,0xC00,0x5FF,0x800,0x1FF,0x3FF,0xA00};

    // ---- per-batch U3 matrices (layer-invariant) ----
    if (tid < NQ) {
        const float* xb  = x  + b * 48 + tid * 4;
        const float* rwi = rw + tid * 12;
        const float* rbi = rb + tid * 3;
        float x0 = xb[0], x1 = xb[1], x2 = xb[2], x3 = xb[3];
        float th = rbi[0] + rwi[0]*x0 + rwi[1]*x1 + rwi[2] *x2 + rwi[3] *x3;
        float ph = rbi[1] + rwi[4]*x0 + rwi[5]*x1 + rwi[6] *x2 + rwi[7] *x3;
        float lm = rbi[2] + rwi[8]*x0 + rwi[9]*x1 + rwi[10]*x2 + rwi[11]*x3;
        float sh, ch, sp, cp, sl, cl;
        sincosf(th * 0.5f, &sh, &ch);
        sincosf(ph,        &sp, &cp);
        sincosf(lm,        &sl, &cl);
        U[tid][0] = make_float2(ch, 0.f);
        U[tid][1] = make_float2(-cl * sh, -sl * sh);
        U[tid][2] = make_float2( cp * sh,  sp * sh);
        U[tid][3] = make_float2((cp*cl - sp*sl) * ch, (cp*sl + sp*cl) * ch);
    }
    __syncthreads();

    // per-thread permutation base: Ltid = L(tid) via suffix-parity scan
    int y = tid; y ^= y >> 1; y ^= y >> 2; y ^= y >> 4;
    const int Ltid  = y | ((y & 1) << 11);
    // swizzled variants: phys(b) = b ^ ((b>>4)&15)
    const int PLtid = Ltid ^ ((Ltid >> 4) & 15);          // for perm-writes
    const int tlo   = tid & 15;                            // A-mapping swizzle key
    const int tB    = tid ^ ((tid >> 4) & 15);             // B-mapping read addr part

    float2 a[16];

    // ===== layer 0: state after 12 U3s on |0..0> is a tensor product =====
    // Built in mapping B: logical idx = (k<<8)|tid; wire w <-> idx bit (11-w).
    {
        float2 base = ((tid >> 7) & 1) ? U[4][2] : U[4][0];
        #pragma unroll
        for (int w = 5; w < 12; w++)
            base = cmul(base, ((tid >> (11 - w)) & 1) ? U[w][2] : U[w][0]);
        float2 phi[4], plo[4];
        #pragma unroll
        for (int i = 0; i < 4; i++) {
            phi[i] = cmul((i & 2) ? U[0][2] : U[0][0], (i & 1) ? U[1][2] : U[1][0]);
            plo[i] = cmul((i & 2) ? U[2][2] : U[2][0], (i & 1) ? U[3][2] : U[3][0]);
        }
        #pragma unroll
        for (int k = 0; k < 16; k++) {
            float2 hi = phi[k >> 2], lo = plo[k & 3];
            a[k] = cmul(base, cmul(hi, lo));
        }
    }

    // perm-write: amp of logical b=(k<<8)|tid goes to phys(L(b)) = PLtid ^ PLK[k]
    #pragma unroll
    for (int k = 0; k < 16; k++)
        st[PLtid ^ (LK[k] ^ ((LK[k] >> 4) & 15))] = a[k];
    __syncthreads();
    // read mapping A (swizzled): logical (tid<<4)|k at phys (tid<<4)|(k^tlo)
    #pragma unroll
    for (int k = 0; k < 16; k++)
        a[k] = st[(tid << 4) | (k ^ tlo)];

    // ===== layers 1,2 =====
    #pragma unroll
    for (int layer = 1; layer < 3; layer++) {
        // A-phase: wires 4..7 via shfl on lane bit (7-w)
        #pragma unroll
        for (int w = 4; w < 8; w++) {
            const int lb = 7 - w;
            float2 u00 = U[w][0], u01 = U[w][1], u10 = U[w][2], u11 = U[w][3];
            bool hi = (lane >> lb) & 1;
            float2 ca = hi ? u11 : u00;
            float2 cb = hi ? u10 : u01;
            #pragma unroll
            for (int k = 0; k < 16; k++) {
                float2 p = shflx(a[k], 1 << lb);
                a[k] = cfma2(ca, a[k], cb, p);
            }
        }
        // A-phase: wires 8..11 register-local on k bit (11-w)
        #pragma unroll
        for (int w = 8; w < 12; w++) {
            const int bp = 11 - w;
            float2 u00 = U[w][0], u01 = U[w][1], u10 = U[w][2], u11 = U[w][3];
            #pragma unroll
            for (int k0 = 0; k0 < 16; k0++) {
                if (k0 & (1 << bp)) continue;
                const int k1 = k0 | (1 << bp);
                float2 a0 = a[k0], a1 = a[k1];
                a[k0] = cfma2(u00, a0, u01, a1);
                a[k1] = cfma2(u10, a0, u11, a1);
            }
        }

        // transpose A -> B (all static indices, swizzled addresses)
        __syncthreads();
        #pragma unroll
        for (int k = 0; k < 16; k++)
            st[(tid << 4) | (k ^ tlo)] = a[k];
        __syncthreads();
        #pragma unroll
        for (int k = 0; k < 16; k++)
            a[k] = st[(k << 8) | tB];

        // B-phase: wires 0..3 register-local on k bit (3-w)
        #pragma unroll
        for (int w = 0; w < 4; w++) {
            const int bp = 3 - w;
            float2 u00 = U[w][0], u01 = U[w][1], u10 = U[w][2], u11 = U[w][3];
            #pragma unroll
            for (int k0 = 0; k0 < 16; k0++) {
                if (k0 & (1 << bp)) continue;
                const int k1 = k0 | (1 << bp);
                float2 a0 = a[k0], a1 = a[k1];
                a[k0] = cfma2(u00, a0, u01, a1);
                a[k1] = cfma2(u10, a0, u11, a1);
            }
        }

        // fused CNOT-ring permutation back to mapping A
        __syncthreads();
        #pragma unroll
        for (int k = 0; k < 16; k++)
            st[PLtid ^ (LK[k] ^ ((LK[k] >> 4) & 15))] = a[k];
        __syncthreads();
        #pragma unroll
        for (int k = 0; k < 16; k++)
            a[k] = st[(tid << 4) | (k ^ tlo)];
    }

    // ---- Pauli-Z expectations (mapping A: bits 11..4 = tid, 3..0 = k) ----
    float psum = 0.f, s8 = 0.f, s9 = 0.f, s10 = 0.f, s11 = 0.f;
    #pragma unroll
    for (int k = 0; k < 16; k++) {
        float pr = a[k].x * a[k].x + a[k].y * a[k].y;
        psum += pr;
        s8  += ((k >> 3) & 1) ? -pr : pr;
        s9  += ((k >> 2) & 1) ? -pr : pr;
        s10 += ((k >> 1) & 1) ? -pr : pr;
        s11 += ( k       & 1) ? -pr : pr;
    }
    float zl[NQ];
    #pragma unroll
    for (int w = 0; w < 8; w++)
        zl[w] = ((tid >> (7 - w)) & 1) ? -psum : psum;
    zl[8] = s8; zl[9] = s9; zl[10] = s10; zl[11] = s11;

    #pragma unroll
    for (int w = 0; w < NQ; w++) {
        #pragma unroll
        for (int off = 16; off > 0; off >>= 1)
            zl[w] += __shfl_xor_sync(0xFFFFFFFFu, zl[w], off);
    }
    if (lane == 0) {
        #pragma unroll
        for (int w = 0; w < NQ; w++) zred[w][warp] = zl[w];
    }
    __syncthreads();
    if (tid < NQ) {
        float z = 0.f;
        #pragma unroll
        for (int j = 0; j < BLK / 32; j++) z += zred[tid][j];
        zfin[tid] = z;
    }
    __syncthreads();

    // ---- MLP: relu(z @ w1^T + b1) @ w2^T + b2 ----
    if (tid < HID) {
        float h = b1[tid];
        #pragma unroll
        for (int i = 0; i < NQ; i++) h += zfin[i] * w1[tid * NQ + i];
        hbuf[tid] = fmaxf(h, 0.f);
    }
    __syncthreads();
    float o = b2[tid];
    #pragma unroll
    for (int j = 0; j < HID; j++) o += hbuf[j] * w2[tid * HID + j];
    out[b * OUTDIM + tid] = o;
}

extern "C" void kernel_launch(void* const* d_in, const int* in_sizes, int n_in,
                              void* d_out, int out_size) {
    const float* x  = (const float*)d_in[0];
    const float* rw = (const float*)d_in[1];
    const float* rb = (const float*)d_in[2];
    const float* w1 = (const float*)d_in[3];
    const float* b1 = (const float*)d_in[4];
    const float* w2 = (const float*)d_in[5];
    const float* b2 = (const float*)d_in[6];
    float* out = (float*)d_out;
    int batch = in_sizes[0] / 48;
    quantum_reupload_kernel<<<batch, BLK>>>(x, rw, rb, w1, b1, w2, b2, out);
}